// round 15
// baseline (speedup 1.0000x reference)
#include <cuda_runtime.h>
#include <cuda_fp16.h>
#include <cstdint>
#include <math.h>

// Problem constants
#define B_   4
#define S_   2048
#define F_   2048
#define H_   16
#define G_   4
#define DH_  128
#define ROT_ 32

#define MTOT (B_*S_)   // 8192
#define QSCALE 0.12751743f   // log2(e)/sqrt(128)

// ---------------------------------------------------------------------------
// Static scratch (fp16)
// ---------------------------------------------------------------------------
__device__ __align__(16) __half g_qhi[MTOT*F_];
__device__ __align__(16) __half g_khi[MTOT*G_*DH_];
__device__ __align__(16) __half g_vhi[MTOT*G_*DH_];
__device__ __align__(16) __half g_xhi[MTOT*F_];
__device__ __align__(16) __half g_ahi[MTOT*F_];
__device__ __align__(16) __half g_wqT_hi[F_*F_];
__device__ __align__(16) __half g_wkT_hi[G_*DH_*F_];
__device__ __align__(16) __half g_wvT_hi[G_*DH_*F_];
__device__ __align__(16) __half g_woT_hi[F_*F_];
__device__ float g_cos[S_*ROT_];
__device__ float g_sin[S_*ROT_];

// ---------------------------------------------------------------------------
// Baseline-legal PTX helpers (sm_80+)
// ---------------------------------------------------------------------------
__device__ __forceinline__ uint32_t smem_u32(const void* p) {
    uint32_t a;
    asm("{ .reg .u64 t; cvta.to.shared.u64 t, %1; cvt.u32.u64 %0, t; }" : "=r"(a) : "l"(p));
    return a;
}
__device__ __forceinline__ void ldsm_x4(uint32_t* r, uint32_t addr) {
    asm volatile("ldmatrix.sync.aligned.m8n8.x4.shared.b16 {%0,%1,%2,%3}, [%4];"
                 : "=r"(r[0]), "=r"(r[1]), "=r"(r[2]), "=r"(r[3]) : "r"(addr));
}
__device__ __forceinline__ void ldsm_x4_t(uint32_t* r, uint32_t addr) {
    asm volatile("ldmatrix.sync.aligned.m8n8.x4.trans.shared.b16 {%0,%1,%2,%3}, [%4];"
                 : "=r"(r[0]), "=r"(r[1]), "=r"(r[2]), "=r"(r[3]) : "r"(addr));
}
__device__ __forceinline__ void mma_f16(float* c, const uint32_t* a, uint32_t b0, uint32_t b1) {
    asm volatile("mma.sync.aligned.m16n8k16.row.col.f32.f16.f16.f32 "
                 "{%0,%1,%2,%3}, {%4,%5,%6,%7}, {%8,%9}, {%0,%1,%2,%3};"
                 : "+f"(c[0]), "+f"(c[1]), "+f"(c[2]), "+f"(c[3])
                 : "r"(a[0]), "r"(a[1]), "r"(a[2]), "r"(a[3]), "r"(b0), "r"(b1));
}
#define CP_ASYNC16(dst, src) \
    asm volatile("cp.async.cg.shared.global [%0], [%1], 16;" :: "r"(dst), "l"(src) : "memory")
#define CP_COMMIT()  asm volatile("cp.async.commit_group;" ::: "memory")
#define CP_WAIT(n)   asm volatile("cp.async.wait_group %0;" :: "n"(n) : "memory")

__device__ __forceinline__ uint32_t pack_h2(float a, float b) {
    __half2 h = __floats2half2_rn(a, b);
    return *(uint32_t*)&h;
}

// ---------------------------------------------------------------------------
// RoPE table init
// ---------------------------------------------------------------------------
__global__ void rope_init_kernel() {
    int idx = blockIdx.x * blockDim.x + threadIdx.x;
    if (idx < S_ * ROT_) {
        int t = idx >> 5, p = idx & 31;
        double freq = pow(10000.0, -((double)(2 * p)) / 64.0);
        double f = (double)t * freq;
        g_cos[idx] = (float)cos(f);
        g_sin[idx] = (float)sin(f);
    }
}

// ---------------------------------------------------------------------------
// fp32 -> fp16 convert (x input)
// ---------------------------------------------------------------------------
__global__ void convert_x_kernel(const float* __restrict__ src,
                                 __half* __restrict__ hi, int n4) {
    int i = blockIdx.x * blockDim.x + threadIdx.x;
    if (i >= n4) return;
    float4 v = ((const float4*)src)[i];
    uint2 o;
    o.x = pack_h2(v.x, v.y);
    o.y = pack_h2(v.z, v.w);
    ((uint2*)hi)[i] = o;
}

// ---------------------------------------------------------------------------
// Merged weight transpose: all 4 weights in one launch.
// blockIdx.x encodes (weight, n-tile): 0..63 wq | 64..79 wk | 80..95 wv | 96..159 wo
// ---------------------------------------------------------------------------
__global__ void transpose_all_kernel(const float* __restrict__ Wq,
                                     const float* __restrict__ Wk,
                                     const float* __restrict__ Wv,
                                     const float* __restrict__ Wo,
                                     __half* __restrict__ Tq,
                                     __half* __restrict__ Tk,
                                     __half* __restrict__ Tv,
                                     __half* __restrict__ To) {
    __shared__ float t[32][33];
    int bx = blockIdx.x;
    const float* W; __half* T; int N;
    if (bx < 64)       { W = Wq; T = Tq; N = F_; }
    else if (bx < 80)  { W = Wk; T = Tk; N = G_ * DH_; bx -= 64; }
    else if (bx < 96)  { W = Wv; T = Tv; N = G_ * DH_; bx -= 80; }
    else               { W = Wo; T = To; N = F_; bx -= 96; }
    const int K = F_;
    int k0 = blockIdx.y * 32, n0 = bx * 32;
    int tx = threadIdx.x, ty = threadIdx.y;   // 32 x 8
#pragma unroll
    for (int j = 0; j < 4; j++)
        t[ty + j * 8][tx] = W[(size_t)(k0 + ty + j * 8) * N + n0 + tx];
    __syncthreads();
#pragma unroll
    for (int j = 0; j < 4; j++) {
        int n = n0 + ty + j * 8, k = k0 + tx;
        T[(size_t)n * K + k] = __float2half_rn(t[tx][ty + j * 8]);
    }
}

// ---------------------------------------------------------------------------
// Shared GEMM body (fp16 1-term, fp32 accum). CTA tile 128x128, BK=32,
// 2-stage cp.async, 8 warps 2(M)x4(N).
// mode: 0 = fp32 out, 1 = Q (rope+scale, fp16), 2 = K (rope, fp16), 3 = V (fp16).
// ---------------------------------------------------------------------------
#define GBK    32
#define TSTR   40                         // smem row stride in fp16 (80 B)
#define TILE_BYTES (128 * TSTR * 2)       // 10240
#define STAGE_BYTES (2 * TILE_BYTES)      // A + B = 20480
#define SMEM_GEMM (2 * STAGE_BYTES)       // 40960

__device__ __forceinline__ void gemm_body(
    uint32_t smem_base, int tid,
    const __half* __restrict__ Ahi,
    const __half* __restrict__ BThi,
    const float* __restrict__ bias,
    float* __restrict__ C,
    __half* __restrict__ Chi,
    size_t rowBase, size_t colBase,
    int N, int K, int mode)
{
    const int wid = tid >> 5;
    const int lid = tid & 31;
    const int warpM = wid & 1;
    const int warpN = wid >> 1;

    const int NC = K / GBK;

    auto prefetch = [&](int stage, int k0) {
        uint32_t st = smem_base + stage * STAGE_BYTES;
#pragma unroll
        for (int t = 0; t < 2; t++) {
            int cidx = tid + t * 256;
            int r  = cidx >> 2;
            int ch = cidx & 3;
            uint32_t doff = r * (TSTR * 2) + ch * 16;
            size_t goffA = (rowBase + r) * (size_t)K + k0 + ch * 8;
            size_t goffB = (colBase + r) * (size_t)K + k0 + ch * 8;
            CP_ASYNC16(st + doff,              (const char*)(Ahi  + goffA));
            CP_ASYNC16(st + TILE_BYTES + doff, (const char*)(BThi + goffB));
        }
        CP_COMMIT();
    };

    float acc[4][4][4];
#pragma unroll
    for (int i = 0; i < 4; i++)
#pragma unroll
        for (int j = 0; j < 4; j++)
#pragma unroll
            for (int q = 0; q < 4; q++) acc[i][j][q] = 0.f;

    const int laneRow = (lid & 7) + ((lid >> 3) & 1) * 8;
    const int laneK   = (lid >> 4) * 8;

    prefetch(0, 0);

    for (int kc = 0; kc < NC; ++kc) {
        const int s = kc & 1;
        if (kc + 1 < NC) prefetch(s ^ 1, (kc + 1) * GBK);
        if (kc + 1 < NC) { CP_WAIT(1); } else { CP_WAIT(0); }
        __syncthreads();

        const uint32_t st = smem_base + s * STAGE_BYTES;
        const uint32_t aHib = st;
        const uint32_t bHib = st + TILE_BYTES;

#pragma unroll
        for (int k16 = 0; k16 < GBK; k16 += 16) {
            const int kk = k16 + laneK;
            uint32_t bH[2][4];
#pragma unroll
            for (int nt = 0; nt < 2; nt++) {
                int row = warpN * 32 + nt * 16 + laneRow;
                uint32_t off = (row * TSTR + kk) * 2;
                ldsm_x4(bH[nt], bHib + off);
            }
#pragma unroll
            for (int mp = 0; mp < 4; mp += 2) {
                uint32_t aH[2][4];
#pragma unroll
                for (int i = 0; i < 2; i++) {
                    int row = warpM * 64 + (mp + i) * 16 + laneRow;
                    uint32_t off = (row * TSTR + kk) * 2;
                    ldsm_x4(aH[i], aHib + off);
                }
#pragma unroll
                for (int i = 0; i < 2; i++)
#pragma unroll
                    for (int nt = 0; nt < 2; nt++) {
                        mma_f16(acc[mp+i][2*nt],   aH[i], bH[nt][0], bH[nt][2]);
                        mma_f16(acc[mp+i][2*nt+1], aH[i], bH[nt][1], bH[nt][3]);
                    }
            }
        }
        __syncthreads();
    }

    // Epilogue
#pragma unroll
    for (int mi = 0; mi < 4; mi++) {
#pragma unroll
        for (int nj = 0; nj < 4; nj++) {
            int row0 = (int)rowBase + warpM * 64 + mi * 16 + (lid >> 2);
            int row1 = row0 + 8;
            int col  = (int)colBase + warpN * 32 + nj * 8 + (lid & 3) * 2;
            float b0 = __ldg(bias + col), b1 = __ldg(bias + col + 1);
            float v0 = acc[mi][nj][0] + b0, v1 = acc[mi][nj][1] + b1;
            float v2 = acc[mi][nj][2] + b0, v3 = acc[mi][nj][3] + b1;
            int d = col & (DH_ - 1);
            if (mode >= 1 && mode <= 2 && d < 64) {   // RoPE for Q,K
                int p = d >> 1;
                int s0 = row0 & (S_ - 1);
                int s1 = row1 & (S_ - 1);
                float c0 = g_cos[s0 * ROT_ + p], sn0 = g_sin[s0 * ROT_ + p];
                float c1 = g_cos[s1 * ROT_ + p], sn1 = g_sin[s1 * ROT_ + p];
                float a0 = v0, bb0 = v1, a1 = v2, bb1 = v3;
                v0 = a0 * c0 - bb0 * sn0;  v1 = bb0 * c0 + a0 * sn0;
                v2 = a1 * c1 - bb1 * sn1;  v3 = bb1 * c1 + a1 * sn1;
            }
            if (mode == 0) {
                *(float2*)(C + (size_t)row0 * N + col) = make_float2(v0, v1);
                *(float2*)(C + (size_t)row1 * N + col) = make_float2(v2, v3);
            } else {
                if (mode == 1) { v0 *= QSCALE; v1 *= QSCALE; v2 *= QSCALE; v3 *= QSCALE; }
                *(uint32_t*)(Chi + (size_t)row0 * N + col) = pack_h2(v0, v1);
                *(uint32_t*)(Chi + (size_t)row1 * N + col) = pack_h2(v2, v3);
            }
        }
    }
}

// ---------------------------------------------------------------------------
// Merged Q/K/V projection: grid (24, 64). bx<16 -> Q, 16..19 -> K, 20..23 -> V.
// ---------------------------------------------------------------------------
__global__ __launch_bounds__(256, 2)
void qkv_proj_kernel(const __half* __restrict__ xhi,
                     const __half* __restrict__ wq,
                     const __half* __restrict__ wk,
                     const __half* __restrict__ wv,
                     const float* __restrict__ bq,
                     const float* __restrict__ bk,
                     const float* __restrict__ bv,
                     __half* __restrict__ qout,
                     __half* __restrict__ kout,
                     __half* __restrict__ vout)
{
    extern __shared__ char smem[];
    const uint32_t smem_base = smem_u32(smem);
    const int bx = blockIdx.x;
    const size_t rowBase = (size_t)blockIdx.y * 128;

    const __half* B;
    const float* bias;
    __half* Chi;
    size_t colBase;
    int N, mode;
    if (bx < 16)      { B = wq; bias = bq; Chi = qout; colBase = (size_t)bx * 128;        N = F_;       mode = 1; }
    else if (bx < 20) { B = wk; bias = bk; Chi = kout; colBase = (size_t)(bx - 16) * 128; N = G_ * DH_; mode = 2; }
    else              { B = wv; bias = bv; Chi = vout; colBase = (size_t)(bx - 20) * 128; N = G_ * DH_; mode = 3; }

    gemm_body(smem_base, threadIdx.x, xhi, B, bias, nullptr, Chi,
              rowBase, colBase, N, F_, mode);
}

// ---------------------------------------------------------------------------
// O projection (fp32 out)
// ---------------------------------------------------------------------------
__global__ __launch_bounds__(256, 2)
void o_proj_kernel(const __half* __restrict__ ahi,
                   const __half* __restrict__ wo,
                   const float* __restrict__ bo,
                   float* __restrict__ out)
{
    extern __shared__ char smem[];
    const uint32_t smem_base = smem_u32(smem);
    gemm_body(smem_base, threadIdx.x, ahi, wo, bo, out, nullptr,
              (size_t)blockIdx.y * 128, (size_t)blockIdx.x * 128, F_, F_, 0);
}

// ---------------------------------------------------------------------------
// Tensor-core flash attention (fp16 operands, fp32 accum, causal, GQA).
// CTA: 64 q rows x 128 kv cols, 4 warps, single K + single V buffer, but
// pipelined in place: K[j+1] loads during softmax, V[j+1] loads during next
// S-MMA (split cp.async commit groups). 2 CTAs/SM.
// ---------------------------------------------------------------------------
#define FSTR   272                 // bytes per smem row (128 fp16 + 8 pad)
#define FTILEB (64 * FSTR)         // 17408 bytes per 64-row tile
#define FKOFF  0                   // K: 128 rows (2 tiles)
#define FVOFF  (2 * FTILEB)        // V: 128 rows (2 tiles)
#define FQOFF  (4 * FTILEB)        // Q: 64 rows  (1 tile)
#define SMEM_FLASH (5 * FTILEB)    // 87040 -> 2 CTAs/SM

__global__ __launch_bounds__(128)
void flash_mma_kernel()
{
    extern __shared__ char fsm[];
    const uint32_t sb = smem_u32(fsm);
    const int tid = threadIdx.x;
    const int wid = tid >> 5;       // 0..3
    const int lid = tid & 31;
    const int qb  = 31 - (int)blockIdx.x;   // 64-row q tile; big tiles first
    const int h   = blockIdx.y;
    const int b   = blockIdx.z;
    const int g   = h >> 2;
    const int qbase = qb * 64;

    const size_t kvstride = (size_t)(G_ * DH_);

    auto load_k = [&](int jblk) {
        size_t base = (((size_t)(b * S_ + jblk * 128)) * G_ + g) * DH_;
#pragma unroll
        for (int i = 0; i < 16; i++) {
            int q = tid + i * 128;
            int r = q >> 4, ch = q & 15;
            CP_ASYNC16(sb + FKOFF + r * FSTR + ch * 16,
                       (const char*)(g_khi + base + (size_t)r * kvstride + ch * 8));
        }
        CP_COMMIT();
    };
    auto load_v = [&](int jblk) {
        size_t base = (((size_t)(b * S_ + jblk * 128)) * G_ + g) * DH_;
#pragma unroll
        for (int i = 0; i < 16; i++) {
            int q = tid + i * 128;
            int r = q >> 4, ch = q & 15;
            CP_ASYNC16(sb + FVOFF + r * FSTR + ch * 16,
                       (const char*)(g_vhi + base + (size_t)r * kvstride + ch * 8));
        }
        CP_COMMIT();
    };

    // Preload: Q (group 0), K0 (group 1), V0 (group 2)
    {
#pragma unroll
        for (int i = 0; i < 8; i++) {
            int q = tid + i * 128;
            int r = q >> 4, ch = q & 15;
            size_t off = (((size_t)(b * S_ + qbase + r)) * H_ + h) * DH_ + ch * 8;
            CP_ASYNC16(sb + FQOFF + r * FSTR + ch * 16, (const char*)(g_qhi + off));
        }
        CP_COMMIT();
    }
    load_k(0);
    load_v(0);

    float O[16][4];
#pragma unroll
    for (int i = 0; i < 16; i++)
#pragma unroll
        for (int q = 0; q < 4; q++) O[i][q] = 0.f;
    float m2[2] = {-1e30f, -1e30f};
    float l2[2] = {0.f, 0.f};

    const int nblocks = qb / 2 + 1;

    const uint32_t qaddrH = sb + FQOFF + (wid * 16 + (lid & 15)) * FSTR + (lid >> 4) * 16;
    const uint32_t lanebase = (lid & 15) * FSTR + (lid >> 4) * 16;
    const int warpRow0 = qbase + wid * 16;

    for (int j = 0; j < nblocks; j++) {
        const bool more = (j + 1 < nblocks);

        // wait K[j] (leaves V[j] possibly in flight)
        CP_WAIT(1);
        __syncthreads();

        const uint32_t kH = sb + FKOFF + lanebase;
        float sacc[16][4];
#pragma unroll
        for (int nb = 0; nb < 16; nb++)
#pragma unroll
            for (int q = 0; q < 4; q++) sacc[nb][q] = 0.f;

#pragma unroll
        for (int kc = 0; kc < 8; kc++) {
            uint32_t qh[4];
            ldsm_x4(qh, qaddrH + kc * 32);
#pragma unroll
            for (int n16 = 0; n16 < 8; n16++) {
                uint32_t rH[4];
                ldsm_x4(rH, kH + n16 * (16 * FSTR) + kc * 32);
                mma_f16(sacc[2*n16],   qh, rH[0], rH[2]);
                mma_f16(sacc[2*n16+1], qh, rH[1], rH[3]);
            }
        }
        __syncthreads();                 // all warps done reading K[j]
        if (more) load_k(j + 1);         // K[j+1] loads during softmax

        // causal mask
        if (j * 128 + 127 > warpRow0) {
#pragma unroll
            for (int nb = 0; nb < 16; nb++)
#pragma unroll
                for (int q = 0; q < 4; q++) {
                    int col = j * 128 + nb * 8 + (lid & 3) * 2 + (q & 1);
                    int row = warpRow0 + (lid >> 2) + (q >> 1) * 8;
                    if (col > row) sacc[nb][q] = -1e30f;
                }
        }

        // online softmax
#pragma unroll
        for (int rh = 0; rh < 2; rh++) {
            float rmax = -1e30f;
#pragma unroll
            for (int nb = 0; nb < 16; nb++)
                rmax = fmaxf(rmax, fmaxf(sacc[nb][rh*2], sacc[nb][rh*2+1]));
            rmax = fmaxf(rmax, __shfl_xor_sync(0xffffffffu, rmax, 1));
            rmax = fmaxf(rmax, __shfl_xor_sync(0xffffffffu, rmax, 2));
            float mnew = fmaxf(m2[rh], rmax);
            float alpha = exp2f(m2[rh] - mnew);
            float rsum = 0.f;
#pragma unroll
            for (int nb = 0; nb < 16; nb++) {
                float p0 = exp2f(sacc[nb][rh*2]   - mnew);
                float p1 = exp2f(sacc[nb][rh*2+1] - mnew);
                sacc[nb][rh*2] = p0; sacc[nb][rh*2+1] = p1;
                rsum += p0 + p1;
            }
            rsum += __shfl_xor_sync(0xffffffffu, rsum, 1);
            rsum += __shfl_xor_sync(0xffffffffu, rsum, 2);
            l2[rh] = l2[rh] * alpha + rsum;
            m2[rh] = mnew;
#pragma unroll
            for (int nb = 0; nb < 16; nb++) {
                O[nb][rh*2]   *= alpha;
                O[nb][rh*2+1] *= alpha;
            }
        }

        // P fragments
        uint32_t ph[8][4];
#pragma unroll
        for (int kc = 0; kc < 8; kc++)
#pragma unroll
            for (int t = 0; t < 4; t++) {
                int nb = 2*kc + (t >> 1);
                ph[kc][t] = pack_h2(sacc[nb][(t & 1) * 2], sacc[nb][(t & 1) * 2 + 1]);
            }

        // wait V[j] (K[j+1] may remain in flight)
        if (more) { CP_WAIT(1); } else { CP_WAIT(0); }
        __syncthreads();

        const uint32_t vb = sb + FVOFF + lanebase;
#pragma unroll
        for (int kc = 0; kc < 8; kc++) {
            uint32_t vrow = vb + kc * (16 * FSTR);
#pragma unroll
            for (int ng = 0; ng < 8; ng++) {
                uint32_t vh[4];
                ldsm_x4_t(vh, vrow + ng * 32);
                mma_f16(O[2*ng],   ph[kc], vh[0], vh[1]);
                mma_f16(O[2*ng+1], ph[kc], vh[2], vh[3]);
            }
        }
        __syncthreads();                 // all warps done reading V[j]
        if (more) load_v(j + 1);         // V[j+1] loads during next S-MMA
    }

    // Epilogue: normalize, write fp16
    const float inv0 = 1.f / l2[0];
    const float inv1 = 1.f / l2[1];
    const int r0 = qbase + wid * 16 + (lid >> 2);
#pragma unroll
    for (int nb = 0; nb < 16; nb++) {
        int col = h * DH_ + nb * 8 + (lid & 3) * 2;
        size_t base0 = ((size_t)(b * S_ + r0)) * F_ + col;
        size_t base1 = ((size_t)(b * S_ + r0 + 8)) * F_ + col;
        *(uint32_t*)(g_ahi + base0) = pack_h2(O[nb][0] * inv0, O[nb][1] * inv0);
        *(uint32_t*)(g_ahi + base1) = pack_h2(O[nb][2] * inv1, O[nb][3] * inv1);
    }
}

// ---------------------------------------------------------------------------
extern "C" void kernel_launch(void* const* d_in, const int* in_sizes, int n_in,
                              void* d_out, int out_size)
{
    const float* x  = (const float*)d_in[0];
    const float* wq = (const float*)d_in[1];
    const float* bq = (const float*)d_in[2];
    const float* wk = (const float*)d_in[3];
    const float* bk = (const float*)d_in[4];
    const float* wv = (const float*)d_in[5];
    const float* bv = (const float*)d_in[6];
    const float* wo = (const float*)d_in[7];
    const float* bo = (const float*)d_in[8];
    float* out = (float*)d_out;

    __half *xhi, *ahi;
    cudaGetSymbolAddress((void**)&xhi, g_xhi);
    cudaGetSymbolAddress((void**)&ahi, g_ahi);
    __half *qhi, *khi, *vhi;
    cudaGetSymbolAddress((void**)&qhi, g_qhi);
    cudaGetSymbolAddress((void**)&khi, g_khi);
    cudaGetSymbolAddress((void**)&vhi, g_vhi);
    __half *wqh, *wkh, *wvh, *woh;
    cudaGetSymbolAddress((void**)&wqh, g_wqT_hi);
    cudaGetSymbolAddress((void**)&wkh, g_wkT_hi);
    cudaGetSymbolAddress((void**)&wvh, g_wvT_hi);
    cudaGetSymbolAddress((void**)&woh, g_woT_hi);

    const int M = MTOT;       // 8192

    rope_init_kernel<<<(S_ * ROT_ + 255) / 256, 256>>>();

    convert_x_kernel<<<(M * F_ / 4 + 255) / 256, 256>>>(x, xhi, M * F_ / 4);

    // All 4 weight transposes in one launch
    transpose_all_kernel<<<dim3(160, F_ / 32), dim3(32, 8)>>>(
        wq, wk, wv, wo, wqh, wkh, wvh, woh);

    cudaFuncSetAttribute(qkv_proj_kernel, cudaFuncAttributeMaxDynamicSharedMemorySize, SMEM_GEMM);
    cudaFuncSetAttribute(o_proj_kernel, cudaFuncAttributeMaxDynamicSharedMemorySize, SMEM_GEMM);

    // Merged Q/K/V projection (all 1-term, RoPE fused for Q,K; Q pre-scaled)
    qkv_proj_kernel<<<dim3(24, M / 128), 256, SMEM_GEMM>>>(
        xhi, wqh, wkh, wvh, bq, bk, bv, qhi, khi, vhi);

    // Flash attention (64 q-rows x 128 kv, in-place KV pipelining, 2 CTAs/SM)
    cudaFuncSetAttribute(flash_mma_kernel, cudaFuncAttributeMaxDynamicSharedMemorySize, SMEM_FLASH);
    flash_mma_kernel<<<dim3(S_ / 64, H_, B_), 128, SMEM_FLASH>>>();

    // Output projection (1-term, fp32 out)
    o_proj_kernel<<<dim3(F_ / 128, M / 128), 256, SMEM_GEMM>>>(ahi, woh, bo, out);
}

// round 16
// speedup vs baseline: 1.1088x; 1.1088x over previous
#include <cuda_runtime.h>
#include <cuda_fp16.h>
#include <cstdint>
#include <math.h>

// Problem constants
#define B_   4
#define S_   2048
#define F_   2048
#define H_   16
#define G_   4
#define DH_  128
#define ROT_ 32

#define MTOT (B_*S_)   // 8192
#define QSCALE 0.12751743f   // log2(e)/sqrt(128)

// ---------------------------------------------------------------------------
// Static scratch (fp16)
// ---------------------------------------------------------------------------
__device__ __align__(16) __half g_qhi[MTOT*F_];
__device__ __align__(16) __half g_khi[MTOT*G_*DH_];
__device__ __align__(16) __half g_vhi[MTOT*G_*DH_];
__device__ __align__(16) __half g_xhi[MTOT*F_];
__device__ __align__(16) __half g_ahi[MTOT*F_];
__device__ __align__(16) __half g_wqT_hi[F_*F_];
__device__ __align__(16) __half g_wkT_hi[G_*DH_*F_];
__device__ __align__(16) __half g_wvT_hi[G_*DH_*F_];
__device__ __align__(16) __half g_woT_hi[F_*F_];
__device__ float g_cos[S_*ROT_];
__device__ float g_sin[S_*ROT_];

// ---------------------------------------------------------------------------
// Baseline-legal PTX helpers (sm_80+)
// ---------------------------------------------------------------------------
__device__ __forceinline__ uint32_t smem_u32(const void* p) {
    uint32_t a;
    asm("{ .reg .u64 t; cvta.to.shared.u64 t, %1; cvt.u32.u64 %0, t; }" : "=r"(a) : "l"(p));
    return a;
}
__device__ __forceinline__ void ldsm_x4(uint32_t* r, uint32_t addr) {
    asm volatile("ldmatrix.sync.aligned.m8n8.x4.shared.b16 {%0,%1,%2,%3}, [%4];"
                 : "=r"(r[0]), "=r"(r[1]), "=r"(r[2]), "=r"(r[3]) : "r"(addr));
}
__device__ __forceinline__ void ldsm_x4_t(uint32_t* r, uint32_t addr) {
    asm volatile("ldmatrix.sync.aligned.m8n8.x4.trans.shared.b16 {%0,%1,%2,%3}, [%4];"
                 : "=r"(r[0]), "=r"(r[1]), "=r"(r[2]), "=r"(r[3]) : "r"(addr));
}
__device__ __forceinline__ void mma_f16(float* c, const uint32_t* a, uint32_t b0, uint32_t b1) {
    asm volatile("mma.sync.aligned.m16n8k16.row.col.f32.f16.f16.f32 "
                 "{%0,%1,%2,%3}, {%4,%5,%6,%7}, {%8,%9}, {%0,%1,%2,%3};"
                 : "+f"(c[0]), "+f"(c[1]), "+f"(c[2]), "+f"(c[3])
                 : "r"(a[0]), "r"(a[1]), "r"(a[2]), "r"(a[3]), "r"(b0), "r"(b1));
}
#define CP_ASYNC16(dst, src) \
    asm volatile("cp.async.cg.shared.global [%0], [%1], 16;" :: "r"(dst), "l"(src) : "memory")
#define CP_COMMIT()  asm volatile("cp.async.commit_group;" ::: "memory")
#define CP_WAIT(n)   asm volatile("cp.async.wait_group %0;" :: "n"(n) : "memory")

__device__ __forceinline__ uint32_t pack_h2(float a, float b) {
    __half2 h = __floats2half2_rn(a, b);
    return *(uint32_t*)&h;
}

// ---------------------------------------------------------------------------
// RoPE table init
// ---------------------------------------------------------------------------
__global__ void rope_init_kernel() {
    int idx = blockIdx.x * blockDim.x + threadIdx.x;
    if (idx < S_ * ROT_) {
        int t = idx >> 5, p = idx & 31;
        double freq = pow(10000.0, -((double)(2 * p)) / 64.0);
        double f = (double)t * freq;
        g_cos[idx] = (float)cos(f);
        g_sin[idx] = (float)sin(f);
    }
}

// ---------------------------------------------------------------------------
// fp32 -> fp16 convert (x input)
// ---------------------------------------------------------------------------
__global__ void convert_x_kernel(const float* __restrict__ src,
                                 __half* __restrict__ hi, int n4) {
    int i = blockIdx.x * blockDim.x + threadIdx.x;
    if (i >= n4) return;
    float4 v = ((const float4*)src)[i];
    uint2 o;
    o.x = pack_h2(v.x, v.y);
    o.y = pack_h2(v.z, v.w);
    ((uint2*)hi)[i] = o;
}

// ---------------------------------------------------------------------------
// Merged weight transpose: all 4 weights in one launch.
// ---------------------------------------------------------------------------
__global__ void transpose_all_kernel(const float* __restrict__ Wq,
                                     const float* __restrict__ Wk,
                                     const float* __restrict__ Wv,
                                     const float* __restrict__ Wo,
                                     __half* __restrict__ Tq,
                                     __half* __restrict__ Tk,
                                     __half* __restrict__ Tv,
                                     __half* __restrict__ To) {
    __shared__ float t[32][33];
    int bx = blockIdx.x;
    const float* W; __half* T; int N;
    if (bx < 64)       { W = Wq; T = Tq; N = F_; }
    else if (bx < 80)  { W = Wk; T = Tk; N = G_ * DH_; bx -= 64; }
    else if (bx < 96)  { W = Wv; T = Tv; N = G_ * DH_; bx -= 80; }
    else               { W = Wo; T = To; N = F_; bx -= 96; }
    const int K = F_;
    int k0 = blockIdx.y * 32, n0 = bx * 32;
    int tx = threadIdx.x, ty = threadIdx.y;   // 32 x 8
#pragma unroll
    for (int j = 0; j < 4; j++)
        t[ty + j * 8][tx] = W[(size_t)(k0 + ty + j * 8) * N + n0 + tx];
    __syncthreads();
#pragma unroll
    for (int j = 0; j < 4; j++) {
        int n = n0 + ty + j * 8, k = k0 + tx;
        T[(size_t)n * K + k] = __float2half_rn(t[tx][ty + j * 8]);
    }
}

// ---------------------------------------------------------------------------
// Shared GEMM body (fp16 1-term, fp32 accum). CTA tile 128x128, BK=64
// (fewer barrier events, deeper MMA runs), 2-stage cp.async, 8 warps 2(M)x4(N).
// mode: 0 = fp32 out, 1 = Q (rope+scale, fp16), 2 = K (rope, fp16), 3 = V (fp16).
// ---------------------------------------------------------------------------
#define GBK    64
#define TSTR   72                         // smem row stride in fp16 (144 B)
#define TILE_BYTES (128 * TSTR * 2)       // 18432
#define STAGE_BYTES (2 * TILE_BYTES)      // A + B = 36864
#define SMEM_GEMM (2 * STAGE_BYTES)       // 73728 -> 2 CTAs/SM

__device__ __forceinline__ void gemm_body(
    uint32_t smem_base, int tid,
    const __half* __restrict__ Ahi,
    const __half* __restrict__ BThi,
    const float* __restrict__ bias,
    float* __restrict__ C,
    __half* __restrict__ Chi,
    size_t rowBase, size_t colBase,
    int N, int K, int mode)
{
    const int wid = tid >> 5;
    const int lid = tid & 31;
    const int warpM = wid & 1;
    const int warpN = wid >> 1;

    const int NC = K / GBK;

    auto prefetch = [&](int stage, int k0) {
        uint32_t st = smem_base + stage * STAGE_BYTES;
#pragma unroll
        for (int t = 0; t < 4; t++) {
            int cidx = tid + t * 256;            // 0..1023
            int r  = cidx >> 3;                  // 0..127
            int ch = cidx & 7;                   // 0..7 (16B chunks)
            uint32_t doff = r * (TSTR * 2) + ch * 16;
            size_t goffA = (rowBase + r) * (size_t)K + k0 + ch * 8;
            size_t goffB = (colBase + r) * (size_t)K + k0 + ch * 8;
            CP_ASYNC16(st + doff,              (const char*)(Ahi  + goffA));
            CP_ASYNC16(st + TILE_BYTES + doff, (const char*)(BThi + goffB));
        }
        CP_COMMIT();
    };

    float acc[4][4][4];
#pragma unroll
    for (int i = 0; i < 4; i++)
#pragma unroll
        for (int j = 0; j < 4; j++)
#pragma unroll
            for (int q = 0; q < 4; q++) acc[i][j][q] = 0.f;

    const int laneRow = (lid & 7) + ((lid >> 3) & 1) * 8;
    const int laneK   = (lid >> 4) * 8;

    prefetch(0, 0);

    for (int kc = 0; kc < NC; ++kc) {
        const int s = kc & 1;
        if (kc + 1 < NC) prefetch(s ^ 1, (kc + 1) * GBK);
        if (kc + 1 < NC) { CP_WAIT(1); } else { CP_WAIT(0); }
        __syncthreads();

        const uint32_t st = smem_base + s * STAGE_BYTES;
        const uint32_t aHib = st;
        const uint32_t bHib = st + TILE_BYTES;

#pragma unroll
        for (int k16 = 0; k16 < GBK; k16 += 16) {
            const int kk = k16 + laneK;
            uint32_t bH[2][4];
#pragma unroll
            for (int nt = 0; nt < 2; nt++) {
                int row = warpN * 32 + nt * 16 + laneRow;
                uint32_t off = (row * TSTR + kk) * 2;
                ldsm_x4(bH[nt], bHib + off);
            }
#pragma unroll
            for (int mp = 0; mp < 4; mp += 2) {
                uint32_t aH[2][4];
#pragma unroll
                for (int i = 0; i < 2; i++) {
                    int row = warpM * 64 + (mp + i) * 16 + laneRow;
                    uint32_t off = (row * TSTR + kk) * 2;
                    ldsm_x4(aH[i], aHib + off);
                }
#pragma unroll
                for (int i = 0; i < 2; i++)
#pragma unroll
                    for (int nt = 0; nt < 2; nt++) {
                        mma_f16(acc[mp+i][2*nt],   aH[i], bH[nt][0], bH[nt][2]);
                        mma_f16(acc[mp+i][2*nt+1], aH[i], bH[nt][1], bH[nt][3]);
                    }
            }
        }
        __syncthreads();
    }

    // Epilogue
#pragma unroll
    for (int mi = 0; mi < 4; mi++) {
#pragma unroll
        for (int nj = 0; nj < 4; nj++) {
            int row0 = (int)rowBase + warpM * 64 + mi * 16 + (lid >> 2);
            int row1 = row0 + 8;
            int col  = (int)colBase + warpN * 32 + nj * 8 + (lid & 3) * 2;
            float b0 = __ldg(bias + col), b1 = __ldg(bias + col + 1);
            float v0 = acc[mi][nj][0] + b0, v1 = acc[mi][nj][1] + b1;
            float v2 = acc[mi][nj][2] + b0, v3 = acc[mi][nj][3] + b1;
            int d = col & (DH_ - 1);
            if (mode >= 1 && mode <= 2 && d < 64) {   // RoPE for Q,K
                int p = d >> 1;
                int s0 = row0 & (S_ - 1);
                int s1 = row1 & (S_ - 1);
                float c0 = g_cos[s0 * ROT_ + p], sn0 = g_sin[s0 * ROT_ + p];
                float c1 = g_cos[s1 * ROT_ + p], sn1 = g_sin[s1 * ROT_ + p];
                float a0 = v0, bb0 = v1, a1 = v2, bb1 = v3;
                v0 = a0 * c0 - bb0 * sn0;  v1 = bb0 * c0 + a0 * sn0;
                v2 = a1 * c1 - bb1 * sn1;  v3 = bb1 * c1 + a1 * sn1;
            }
            if (mode == 0) {
                *(float2*)(C + (size_t)row0 * N + col) = make_float2(v0, v1);
                *(float2*)(C + (size_t)row1 * N + col) = make_float2(v2, v3);
            } else {
                if (mode == 1) { v0 *= QSCALE; v1 *= QSCALE; v2 *= QSCALE; v3 *= QSCALE; }
                *(uint32_t*)(Chi + (size_t)row0 * N + col) = pack_h2(v0, v1);
                *(uint32_t*)(Chi + (size_t)row1 * N + col) = pack_h2(v2, v3);
            }
        }
    }
}

// ---------------------------------------------------------------------------
// Merged Q/K/V projection: grid (24, 64). bx<16 -> Q, 16..19 -> K, 20..23 -> V.
// ---------------------------------------------------------------------------
__global__ __launch_bounds__(256, 2)
void qkv_proj_kernel(const __half* __restrict__ xhi,
                     const __half* __restrict__ wq,
                     const __half* __restrict__ wk,
                     const __half* __restrict__ wv,
                     const float* __restrict__ bq,
                     const float* __restrict__ bk,
                     const float* __restrict__ bv,
                     __half* __restrict__ qout,
                     __half* __restrict__ kout,
                     __half* __restrict__ vout)
{
    extern __shared__ char smem[];
    const uint32_t smem_base = smem_u32(smem);
    const int bx = blockIdx.x;
    const size_t rowBase = (size_t)blockIdx.y * 128;

    const __half* B;
    const float* bias;
    __half* Chi;
    size_t colBase;
    int N, mode;
    if (bx < 16)      { B = wq; bias = bq; Chi = qout; colBase = (size_t)bx * 128;        N = F_;       mode = 1; }
    else if (bx < 20) { B = wk; bias = bk; Chi = kout; colBase = (size_t)(bx - 16) * 128; N = G_ * DH_; mode = 2; }
    else              { B = wv; bias = bv; Chi = vout; colBase = (size_t)(bx - 20) * 128; N = G_ * DH_; mode = 3; }

    gemm_body(smem_base, threadIdx.x, xhi, B, bias, nullptr, Chi,
              rowBase, colBase, N, F_, mode);
}

// ---------------------------------------------------------------------------
// O projection (fp32 out)
// ---------------------------------------------------------------------------
__global__ __launch_bounds__(256, 2)
void o_proj_kernel(const __half* __restrict__ ahi,
                   const __half* __restrict__ wo,
                   const float* __restrict__ bo,
                   float* __restrict__ out)
{
    extern __shared__ char smem[];
    const uint32_t smem_base = smem_u32(smem);
    gemm_body(smem_base, threadIdx.x, ahi, wo, bo, out, nullptr,
              (size_t)blockIdx.y * 128, (size_t)blockIdx.x * 128, F_, F_, 0);
}

// ---------------------------------------------------------------------------
// Tensor-core flash attention (fp16 operands, fp32 accum, causal, GQA).
// R14 version: 64 q rows x 128 kv cols, 4 warps, single KV buffer loaded
// per iteration, 2 CTAs/SM for cross-CTA phase overlap.
// ---------------------------------------------------------------------------
#define FSTR   272                 // bytes per smem row (128 fp16 + 8 pad)
#define FTILEB (64 * FSTR)         // 17408
#define FKOFF  0
#define FVOFF  (2 * FTILEB)
#define FQOFF  (4 * FTILEB)
#define SMEM_FLASH (5 * FTILEB)    // 87040 -> 2 CTAs/SM

__global__ __launch_bounds__(128)
void flash_mma_kernel()
{
    extern __shared__ char fsm[];
    const uint32_t sb = smem_u32(fsm);
    const int tid = threadIdx.x;
    const int wid = tid >> 5;
    const int lid = tid & 31;
    const int qb  = 31 - (int)blockIdx.x;
    const int h   = blockIdx.y;
    const int b   = blockIdx.z;
    const int g   = h >> 2;
    const int qbase = qb * 64;

#pragma unroll
    for (int i = 0; i < 8; i++) {
        int q = tid + i * 128;
        int r = q >> 4, ch = q & 15;
        size_t off = (((size_t)(b * S_ + qbase + r)) * H_ + h) * DH_ + ch * 8;
        CP_ASYNC16(sb + FQOFF + r * FSTR + ch * 16, (const char*)(g_qhi + off));
    }
    CP_COMMIT();
    CP_WAIT(0);

    float O[16][4];
#pragma unroll
    for (int i = 0; i < 16; i++)
#pragma unroll
        for (int q = 0; q < 4; q++) O[i][q] = 0.f;
    float m2[2] = {-1e30f, -1e30f};
    float l2[2] = {0.f, 0.f};

    const int nblocks = qb / 2 + 1;

    const uint32_t qaddrH = sb + FQOFF + (wid * 16 + (lid & 15)) * FSTR + (lid >> 4) * 16;
    const uint32_t lanebase = (lid & 15) * FSTR + (lid >> 4) * 16;
    const int warpRow0 = qbase + wid * 16;

    for (int j = 0; j < nblocks; j++) {
        __syncthreads();
        {
            size_t base = (((size_t)(b * S_ + j * 128)) * G_ + g) * DH_;
#pragma unroll
            for (int i = 0; i < 16; i++) {
                int q = tid + i * 128;
                int r = q >> 4, ch = q & 15;
                size_t off = base + (size_t)r * (G_ * DH_) + ch * 8;
                uint32_t d = r * FSTR + ch * 16;
                CP_ASYNC16(sb + FKOFF + d, (const char*)(g_khi + off));
                CP_ASYNC16(sb + FVOFF + d, (const char*)(g_vhi + off));
            }
            CP_COMMIT();
            CP_WAIT(0);
        }
        __syncthreads();

        const uint32_t kH = sb + FKOFF + lanebase;

        float sacc[16][4];
#pragma unroll
        for (int nb = 0; nb < 16; nb++)
#pragma unroll
            for (int q = 0; q < 4; q++) sacc[nb][q] = 0.f;

#pragma unroll
        for (int kc = 0; kc < 8; kc++) {
            uint32_t qh[4];
            ldsm_x4(qh, qaddrH + kc * 32);
#pragma unroll
            for (int n16 = 0; n16 < 8; n16++) {
                uint32_t rH[4];
                ldsm_x4(rH, kH + n16 * (16 * FSTR) + kc * 32);
                mma_f16(sacc[2*n16],   qh, rH[0], rH[2]);
                mma_f16(sacc[2*n16+1], qh, rH[1], rH[3]);
            }
        }

        if (j * 128 + 127 > warpRow0) {
#pragma unroll
            for (int nb = 0; nb < 16; nb++)
#pragma unroll
                for (int q = 0; q < 4; q++) {
                    int col = j * 128 + nb * 8 + (lid & 3) * 2 + (q & 1);
                    int row = warpRow0 + (lid >> 2) + (q >> 1) * 8;
                    if (col > row) sacc[nb][q] = -1e30f;
                }
        }

#pragma unroll
        for (int rh = 0; rh < 2; rh++) {
            float rmax = -1e30f;
#pragma unroll
            for (int nb = 0; nb < 16; nb++)
                rmax = fmaxf(rmax, fmaxf(sacc[nb][rh*2], sacc[nb][rh*2+1]));
            rmax = fmaxf(rmax, __shfl_xor_sync(0xffffffffu, rmax, 1));
            rmax = fmaxf(rmax, __shfl_xor_sync(0xffffffffu, rmax, 2));
            float mnew = fmaxf(m2[rh], rmax);
            float alpha = exp2f(m2[rh] - mnew);
            float rsum = 0.f;
#pragma unroll
            for (int nb = 0; nb < 16; nb++) {
                float p0 = exp2f(sacc[nb][rh*2]   - mnew);
                float p1 = exp2f(sacc[nb][rh*2+1] - mnew);
                sacc[nb][rh*2] = p0; sacc[nb][rh*2+1] = p1;
                rsum += p0 + p1;
            }
            rsum += __shfl_xor_sync(0xffffffffu, rsum, 1);
            rsum += __shfl_xor_sync(0xffffffffu, rsum, 2);
            l2[rh] = l2[rh] * alpha + rsum;
            m2[rh] = mnew;
#pragma unroll
            for (int nb = 0; nb < 16; nb++) {
                O[nb][rh*2]   *= alpha;
                O[nb][rh*2+1] *= alpha;
            }
        }

        uint32_t ph[8][4];
#pragma unroll
        for (int kc = 0; kc < 8; kc++)
#pragma unroll
            for (int t = 0; t < 4; t++) {
                int nb = 2*kc + (t >> 1);
                ph[kc][t] = pack_h2(sacc[nb][(t & 1) * 2], sacc[nb][(t & 1) * 2 + 1]);
            }

        const uint32_t vb = sb + FVOFF + lanebase;
#pragma unroll
        for (int kc = 0; kc < 8; kc++) {
            uint32_t vrow = vb + kc * (16 * FSTR);
#pragma unroll
            for (int ng = 0; ng < 8; ng++) {
                uint32_t vh[4];
                ldsm_x4_t(vh, vrow + ng * 32);
                mma_f16(O[2*ng],   ph[kc], vh[0], vh[1]);
                mma_f16(O[2*ng+1], ph[kc], vh[2], vh[3]);
            }
        }
    }

    const float inv0 = 1.f / l2[0];
    const float inv1 = 1.f / l2[1];
    const int r0 = qbase + wid * 16 + (lid >> 2);
#pragma unroll
    for (int nb = 0; nb < 16; nb++) {
        int col = h * DH_ + nb * 8 + (lid & 3) * 2;
        size_t base0 = ((size_t)(b * S_ + r0)) * F_ + col;
        size_t base1 = ((size_t)(b * S_ + r0 + 8)) * F_ + col;
        *(uint32_t*)(g_ahi + base0) = pack_h2(O[nb][0] * inv0, O[nb][1] * inv0);
        *(uint32_t*)(g_ahi + base1) = pack_h2(O[nb][2] * inv1, O[nb][3] * inv1);
    }
}

// ---------------------------------------------------------------------------
extern "C" void kernel_launch(void* const* d_in, const int* in_sizes, int n_in,
                              void* d_out, int out_size)
{
    const float* x  = (const float*)d_in[0];
    const float* wq = (const float*)d_in[1];
    const float* bq = (const float*)d_in[2];
    const float* wk = (const float*)d_in[3];
    const float* bk = (const float*)d_in[4];
    const float* wv = (const float*)d_in[5];
    const float* bv = (const float*)d_in[6];
    const float* wo = (const float*)d_in[7];
    const float* bo = (const float*)d_in[8];
    float* out = (float*)d_out;

    __half *xhi, *ahi;
    cudaGetSymbolAddress((void**)&xhi, g_xhi);
    cudaGetSymbolAddress((void**)&ahi, g_ahi);
    __half *qhi, *khi, *vhi;
    cudaGetSymbolAddress((void**)&qhi, g_qhi);
    cudaGetSymbolAddress((void**)&khi, g_khi);
    cudaGetSymbolAddress((void**)&vhi, g_vhi);
    __half *wqh, *wkh, *wvh, *woh;
    cudaGetSymbolAddress((void**)&wqh, g_wqT_hi);
    cudaGetSymbolAddress((void**)&wkh, g_wkT_hi);
    cudaGetSymbolAddress((void**)&wvh, g_wvT_hi);
    cudaGetSymbolAddress((void**)&woh, g_woT_hi);

    const int M = MTOT;       // 8192

    rope_init_kernel<<<(S_ * ROT_ + 255) / 256, 256>>>();

    convert_x_kernel<<<(M * F_ / 4 + 255) / 256, 256>>>(x, xhi, M * F_ / 4);

    transpose_all_kernel<<<dim3(160, F_ / 32), dim3(32, 8)>>>(
        wq, wk, wv, wo, wqh, wkh, wvh, woh);

    cudaFuncSetAttribute(qkv_proj_kernel, cudaFuncAttributeMaxDynamicSharedMemorySize, SMEM_GEMM);
    cudaFuncSetAttribute(o_proj_kernel, cudaFuncAttributeMaxDynamicSharedMemorySize, SMEM_GEMM);

    // Merged Q/K/V projection (all 1-term, RoPE fused for Q,K; Q pre-scaled)
    qkv_proj_kernel<<<dim3(24, M / 128), 256, SMEM_GEMM>>>(
        xhi, wqh, wkh, wvh, bq, bk, bv, qhi, khi, vhi);

    // Flash attention (R14 config: 64x128, single KV buffer, 2 CTAs/SM)
    cudaFuncSetAttribute(flash_mma_kernel, cudaFuncAttributeMaxDynamicSharedMemorySize, SMEM_FLASH);
    flash_mma_kernel<<<dim3(S_ / 64, H_, B_), 128, SMEM_FLASH>>>();

    // Output projection (1-term, fp32 out)
    o_proj_kernel<<<dim3(F_ / 128, M / 128), 256, SMEM_GEMM>>>(ahi, woh, bo, out);
}